// round 1
// baseline (speedup 1.0000x reference)
#include <cuda_runtime.h>
#include <math.h>

// Problem constants
#define NN 100000
#define EE 300000
#define IN_DIM 10
#define HID 384
#define TT 5
#define BN_EPS 1e-5f

// Static scratch (allocation-free rule: __device__ globals)
__device__ float g_bufA[(size_t)NN * HID];
__device__ float g_bufB[(size_t)NN * HID];
__device__ float g_agg [(size_t)NN * HID];
__device__ float g_cnt [NN];
__device__ float g_inv [NN];

// ---------------------------------------------------------------------------
// degree count + inverse
// ---------------------------------------------------------------------------
__global__ void k_count(const int* __restrict__ dst, float* __restrict__ cnt, int e) {
    int i = blockIdx.x * blockDim.x + threadIdx.x;
    if (i < e) atomicAdd(&cnt[dst[i]], 1.0f);
}

__global__ void k_inv(const float* __restrict__ cnt, float* __restrict__ inv, int n) {
    int i = blockIdx.x * blockDim.x + threadIdx.x;
    if (i < n) inv[i] = 1.0f / fmaxf(cnt[i], 1.0f);
}

// ---------------------------------------------------------------------------
// scatter-add: layer 0 (F=10)
// ---------------------------------------------------------------------------
__global__ void k_scatter10(const int* __restrict__ src, const int* __restrict__ dst,
                            const float* __restrict__ x, float* __restrict__ agg, int e) {
    int idx = blockIdx.x * blockDim.x + threadIdx.x;
    if (idx >= e * IN_DIM) return;
    int ed = idx / IN_DIM;
    int f  = idx % IN_DIM;
    atomicAdd(&agg[(size_t)dst[ed] * IN_DIM + f], x[(size_t)src[ed] * IN_DIM + f]);
}

// ---------------------------------------------------------------------------
// scatter-add: hidden layers (F=384), float4 chunks (96 per edge)
// ---------------------------------------------------------------------------
__global__ void k_scatter384(const int* __restrict__ src, const int* __restrict__ dst,
                             const float* __restrict__ h, float* __restrict__ agg, int e) {
    int idx = blockIdx.x * blockDim.x + threadIdx.x;
    if (idx >= e * 96) return;
    int ed = idx / 96;
    int c  = (idx % 96) * 4;
    int s = src[ed], d = dst[ed];
    float4 v = *(const float4*)(h + (size_t)s * HID + c);
    float* p = agg + (size_t)d * HID + c;
    atomicAdd(p + 0, v.x);
    atomicAdd(p + 1, v.y);
    atomicAdd(p + 2, v.z);
    atomicAdd(p + 3, v.w);
}

// ---------------------------------------------------------------------------
// Layer 0 SAGE: K=10. 8 rows/block, 384 threads (one per out col).
// out = (agg/cnt)@Wl^T + b + x@Wr^T ; L2-normalize row; BN; ELU
// ---------------------------------------------------------------------------
__global__ void k_layer0(const float* __restrict__ agg, const float* __restrict__ x,
                         const float* __restrict__ invc,
                         const float* __restrict__ Wl, const float* __restrict__ bl,
                         const float* __restrict__ Wr,
                         const float* __restrict__ bng, const float* __restrict__ bnb,
                         const float* __restrict__ bnm, const float* __restrict__ bnv,
                         float* __restrict__ out, int n) {
    __shared__ float sA[8][IN_DIM];
    __shared__ float sX[8][IN_DIM];
    __shared__ float sInv[8];
    __shared__ float red[8];
    int t = threadIdx.x;
    int row0 = blockIdx.x * 8;

    if (t < 80) {
        int r = t / IN_DIM, k = t % IN_DIM;
        int row = row0 + r;
        sA[r][k] = (row < n) ? agg[(size_t)row * IN_DIM + k] : 0.0f;
    } else if (t < 160) {
        int q = t - 80;
        int r = q / IN_DIM, k = q % IN_DIM;
        int row = row0 + r;
        sX[r][k] = (row < n) ? x[(size_t)row * IN_DIM + k] : 0.0f;
    } else if (t < 168) {
        int r = t - 160, row = row0 + r;
        sInv[r] = (row < n) ? invc[row] : 1.0f;
    } else if (t < 176) {
        red[t - 168] = 0.0f;
    }
    __syncthreads();

    int j = t;  // output column 0..383
    float wl[IN_DIM], wr[IN_DIM];
#pragma unroll
    for (int k = 0; k < IN_DIM; k++) {
        wl[k] = Wl[j * IN_DIM + k];
        wr[k] = Wr[j * IN_DIM + k];
    }
    float bb = bl[j];

    float v[8];
#pragma unroll
    for (int r = 0; r < 8; r++) {
        float iv = sInv[r];
        float s = bb;
#pragma unroll
        for (int k = 0; k < IN_DIM; k++)
            s += sA[r][k] * iv * wl[k] + sX[r][k] * wr[k];
        v[r] = s;
    }

    int lane = t & 31;
#pragma unroll
    for (int r = 0; r < 8; r++) {
        float p = v[r] * v[r];
#pragma unroll
        for (int o = 16; o > 0; o >>= 1) p += __shfl_xor_sync(0xFFFFFFFFu, p, o);
        if (lane == 0) atomicAdd(&red[r], p);
    }
    __syncthreads();

    float gm = bng[j], gb = bnb[j], mm = bnm[j], vv = bnv[j];
    float bscale = rsqrtf(vv + BN_EPS) * gm;
#pragma unroll
    for (int r = 0; r < 8; r++) {
        int row = row0 + r;
        if (row >= n) continue;
        float sc = 1.0f / fmaxf(sqrtf(red[r]), 1e-12f);
        float val = v[r] * sc;
        val = (val - mm) * bscale + gb;
        val = (val > 0.0f) ? val : expm1f(val);
        out[(size_t)row * HID + j] = val;
    }
}

// ---------------------------------------------------------------------------
// Big fused GEMM: C[64, 384] tile, 512 threads, 48 acc/thread (8 rows x 6 cols)
//   C = A1 * W1^T (+ A2 * W2^T) + bias ; optional invc row-scale on A1
//   epi 0: L2-normalize row, BN, ELU   (SAGE layers)
//   epi 1: BN, ReLU                    (projection MLP)
// K fixed at 384.
// ---------------------------------------------------------------------------
__global__ void __launch_bounds__(512, 1)
k_gemm(const float* __restrict__ A1, const float* __restrict__ W1,
       const float* __restrict__ bias,
       const float* __restrict__ A2, const float* __restrict__ W2,
       const float* __restrict__ invc,
       const float* __restrict__ bng, const float* __restrict__ bnb,
       const float* __restrict__ bnm, const float* __restrict__ bnv,
       float* __restrict__ out, int nrows, int epi) {
    __shared__ float As[64][17];
    __shared__ float Ws[16][385];
    __shared__ float red[64];

    const int tid = threadIdx.x;
    const int rg = tid >> 6;          // 0..7  (8 rows each)
    const int cg = tid & 63;          // 0..63 (6 cols each)
    const int row_base = blockIdx.x * 64;

    float acc[8][6];
#pragma unroll
    for (int i = 0; i < 8; i++)
#pragma unroll
        for (int j = 0; j < 6; j++) acc[i][j] = 0.0f;

    for (int pass = 0; pass < 2; pass++) {
        const float* A = (pass == 0) ? A1 : A2;
        const float* W = (pass == 0) ? W1 : W2;
        if (A == nullptr) break;
        const bool scaleA = (pass == 0) && (invc != nullptr);

        for (int k0 = 0; k0 < HID; k0 += 16) {
            // load A tile [64 rows x 16 k]
#pragma unroll
            for (int l = 0; l < 2; l++) {
                int lin = tid + l * 512;
                int r = lin >> 4, kk = lin & 15;
                int row = row_base + r;
                float v = 0.0f;
                if (row < nrows) {
                    v = A[(size_t)row * HID + k0 + kk];
                    if (scaleA) v *= invc[row];
                }
                As[r][kk] = v;
            }
            // load W tile [16 k x 384 cols]
#pragma unroll
            for (int l = 0; l < 12; l++) {
                int lin = tid + l * 512;
                int kk = lin & 15, j = lin >> 4;
                Ws[kk][j] = W[(size_t)j * HID + k0 + kk];
            }
            __syncthreads();

#pragma unroll
            for (int kk = 0; kk < 16; kk++) {
                float a[8], w[6];
#pragma unroll
                for (int i = 0; i < 8; i++) a[i] = As[rg * 8 + i][kk];
#pragma unroll
                for (int j = 0; j < 6; j++) w[j] = Ws[kk][cg * 6 + j];
#pragma unroll
                for (int i = 0; i < 8; i++)
#pragma unroll
                    for (int j = 0; j < 6; j++) acc[i][j] = fmaf(a[i], w[j], acc[i][j]);
            }
            __syncthreads();
        }
    }

    // bias
#pragma unroll
    for (int j = 0; j < 6; j++) {
        float b = bias[cg * 6 + j];
#pragma unroll
        for (int i = 0; i < 8; i++) acc[i][j] += b;
    }

    const int lane = tid & 31;

    if (epi == 0) {
        // L2 row norm
        if (tid < 64) red[tid] = 0.0f;
        __syncthreads();
#pragma unroll
        for (int i = 0; i < 8; i++) {
            float p = 0.0f;
#pragma unroll
            for (int j = 0; j < 6; j++) p += acc[i][j] * acc[i][j];
#pragma unroll
            for (int o = 16; o > 0; o >>= 1) p += __shfl_xor_sync(0xFFFFFFFFu, p, o);
            if (lane == 0) atomicAdd(&red[rg * 8 + i], p);
        }
        __syncthreads();

        float gm[6], gb[6], sm2[6], mm[6];
#pragma unroll
        for (int j = 0; j < 6; j++) {
            int c = cg * 6 + j;
            gm[j] = bng[c]; gb[j] = bnb[c]; mm[j] = bnm[c];
            sm2[j] = rsqrtf(bnv[c] + BN_EPS) * gm[j];
        }
#pragma unroll
        for (int i = 0; i < 8; i++) {
            int row = row_base + rg * 8 + i;
            if (row >= nrows) continue;
            float sc = 1.0f / fmaxf(sqrtf(red[rg * 8 + i]), 1e-12f);
#pragma unroll
            for (int j = 0; j < 6; j++) {
                int c = cg * 6 + j;
                float v = acc[i][j] * sc;
                v = (v - mm[j]) * sm2[j] + gb[j];
                v = (v > 0.0f) ? v : expm1f(v);
                out[(size_t)row * HID + c] = v;
            }
        }
    } else {
        float gb[6], sm2[6], mm[6];
#pragma unroll
        for (int j = 0; j < 6; j++) {
            int c = cg * 6 + j;
            gb[j] = bnb[c]; mm[j] = bnm[c];
            sm2[j] = rsqrtf(bnv[c] + BN_EPS) * bng[c];
        }
#pragma unroll
        for (int i = 0; i < 8; i++) {
            int row = row_base + rg * 8 + i;
            if (row >= nrows) continue;
#pragma unroll
            for (int j = 0; j < 6; j++) {
                int c = cg * 6 + j;
                float v = (acc[i][j] - mm[j]) * sm2[j] + gb[j];
                v = fmaxf(v, 0.0f);
                out[(size_t)row * HID + c] = v;
            }
        }
    }
}

// ---------------------------------------------------------------------------
// Final projection: out[N,3] = h @ Wp2^T + bp2. One warp per row.
// ---------------------------------------------------------------------------
__global__ void k_final(const float* __restrict__ h, const float* __restrict__ W,
                        const float* __restrict__ b, float* __restrict__ out, int n) {
    int w = (blockIdx.x * blockDim.x + threadIdx.x) >> 5;
    int lane = threadIdx.x & 31;
    if (w >= n) return;
    const float* hr = h + (size_t)w * HID;
    float a0 = 0.0f, a1 = 0.0f, a2 = 0.0f;
#pragma unroll
    for (int k = lane; k < HID; k += 32) {
        float hv = hr[k];
        a0 = fmaf(hv, W[k], a0);
        a1 = fmaf(hv, W[HID + k], a1);
        a2 = fmaf(hv, W[2 * HID + k], a2);
    }
#pragma unroll
    for (int o = 16; o > 0; o >>= 1) {
        a0 += __shfl_xor_sync(0xFFFFFFFFu, a0, o);
        a1 += __shfl_xor_sync(0xFFFFFFFFu, a1, o);
        a2 += __shfl_xor_sync(0xFFFFFFFFu, a2, o);
    }
    if (lane == 0) {
        out[(size_t)w * 3 + 0] = a0 + b[0];
        out[(size_t)w * 3 + 1] = a1 + b[1];
        out[(size_t)w * 3 + 2] = a2 + b[2];
    }
}

// ---------------------------------------------------------------------------
extern "C" void kernel_launch(void* const* d_in, const int* in_sizes, int n_in,
                              void* d_out, int out_size) {
    const float* x    = (const float*)d_in[0];
    const int*   ei   = (const int*)  d_in[1];
    const float* Wl0  = (const float*)d_in[2];
    const float* bl0  = (const float*)d_in[3];
    const float* Wr0  = (const float*)d_in[4];
    const float* Wl   = (const float*)d_in[5];
    const float* bl   = (const float*)d_in[6];
    const float* Wr   = (const float*)d_in[7];
    const float* bng  = (const float*)d_in[8];
    const float* bnb  = (const float*)d_in[9];
    const float* bnm  = (const float*)d_in[10];
    const float* bnv  = (const float*)d_in[11];
    const float* Wp0  = (const float*)d_in[12];
    const float* bp0  = (const float*)d_in[13];
    const float* Wp1  = (const float*)d_in[14];
    const float* bp1  = (const float*)d_in[15];
    const float* Wp2  = (const float*)d_in[16];
    const float* bp2  = (const float*)d_in[17];
    const float* pg   = (const float*)d_in[18];
    const float* pb   = (const float*)d_in[19];
    const float* pm   = (const float*)d_in[20];
    const float* pv   = (const float*)d_in[21];

    const int* src = ei;
    const int* dst = ei + EE;

    float *hA, *hB, *agg, *cnt, *inv;
    cudaGetSymbolAddress((void**)&hA,  g_bufA);
    cudaGetSymbolAddress((void**)&hB,  g_bufB);
    cudaGetSymbolAddress((void**)&agg, g_agg);
    cudaGetSymbolAddress((void**)&cnt, g_cnt);
    cudaGetSymbolAddress((void**)&inv, g_inv);

    // degree + inverse
    cudaMemsetAsync(cnt, 0, (size_t)NN * sizeof(float));
    k_count<<<(EE + 255) / 256, 256>>>(dst, cnt, EE);
    k_inv<<<(NN + 255) / 256, 256>>>(cnt, inv, NN);

    // layer 0 (K=10)
    cudaMemsetAsync(agg, 0, (size_t)NN * IN_DIM * sizeof(float));
    k_scatter10<<<(EE * IN_DIM + 255) / 256, 256>>>(src, dst, x, agg, EE);
    k_layer0<<<(NN + 7) / 8, 384>>>(agg, x, inv, Wl0, bl0, Wr0,
                                    bng, bnb, bnm, bnv, hA, NN);

    // layers 1..4 (K=384 dual GEMM)
    const int gblocks = (NN + 63) / 64;
    for (int t = 1; t < TT; t++) {
        cudaMemsetAsync(agg, 0, (size_t)NN * HID * sizeof(float));
        k_scatter384<<<(EE * 96 + 255) / 256, 256>>>(src, dst, hA, agg, EE);
        k_gemm<<<gblocks, 512>>>(agg, Wl + (size_t)(t - 1) * HID * HID, bl + (t - 1) * HID,
                                 hA,  Wr + (size_t)(t - 1) * HID * HID,
                                 inv,
                                 bng + t * HID, bnb + t * HID, bnm + t * HID, bnv + t * HID,
                                 hB, NN, 0);
        float* tmp = hA; hA = hB; hB = tmp;
    }

    // projection MLP
    k_gemm<<<gblocks, 512>>>(hA, Wp0, bp0, nullptr, nullptr, nullptr,
                             pg, pb, pm, pv, hB, NN, 1);
    k_gemm<<<gblocks, 512>>>(hB, Wp1, bp1, nullptr, nullptr, nullptr,
                             pg + HID, pb + HID, pm + HID, pv + HID, hA, NN, 1);
    k_final<<<(NN + 7) / 8, 256>>>(hA, Wp2, bp2, (float*)d_out, NN);

    (void)in_sizes; (void)n_in; (void)out_size;
}

// round 4
// speedup vs baseline: 3.2580x; 3.2580x over previous
#include <cuda_runtime.h>
#include <math.h>
#include <cstdint>

#define NN 100000
#define EE 300000
#define IN_DIM 10
#define HID 384
#define TT 5
#define BN_EPS 1e-5f

// Static scratch (allocation-free rule)
__device__ float g_bufA[(size_t)NN * HID];
__device__ float g_bufB[(size_t)NN * HID];
__device__ float g_agg [(size_t)NN * HID];
__device__ float g_cnt [NN];
__device__ float g_inv [NN];

// ---------------------------------------------------------------------------
// helpers
// ---------------------------------------------------------------------------
__device__ __forceinline__ uint32_t f2tf32(float f) {
    uint32_t u;
    asm("cvt.rna.tf32.f32 %0, %1;" : "=r"(u) : "f"(f));
    return u;
}

__device__ __forceinline__ void mma_tf32(float* c,
                                         uint32_t a0, uint32_t a1, uint32_t a2, uint32_t a3,
                                         uint32_t b0, uint32_t b1) {
    asm volatile("mma.sync.aligned.m16n8k8.row.col.f32.tf32.tf32.f32 "
                 "{%0,%1,%2,%3}, {%4,%5,%6,%7}, {%8,%9}, {%0,%1,%2,%3};"
                 : "+f"(c[0]), "+f"(c[1]), "+f"(c[2]), "+f"(c[3])
                 : "r"(a0), "r"(a1), "r"(a2), "r"(a3), "r"(b0), "r"(b1));
}

// ---------------------------------------------------------------------------
// degree count + inverse
// ---------------------------------------------------------------------------
__global__ void k_count(const int* __restrict__ dst, float* __restrict__ cnt, int e) {
    int i = blockIdx.x * blockDim.x + threadIdx.x;
    if (i < e) atomicAdd(&cnt[dst[i]], 1.0f);
}
__global__ void k_inv(const float* __restrict__ cnt, float* __restrict__ inv, int n) {
    int i = blockIdx.x * blockDim.x + threadIdx.x;
    if (i < n) inv[i] = 1.0f / fmaxf(cnt[i], 1.0f);
}

// ---------------------------------------------------------------------------
// scatter-add kernels
// ---------------------------------------------------------------------------
__global__ void k_scatter10(const int* __restrict__ src, const int* __restrict__ dst,
                            const float* __restrict__ x, float* __restrict__ agg, int e) {
    int idx = blockIdx.x * blockDim.x + threadIdx.x;
    if (idx >= e * IN_DIM) return;
    int ed = idx / IN_DIM;
    int f  = idx % IN_DIM;
    atomicAdd(&agg[(size_t)dst[ed] * IN_DIM + f], x[(size_t)src[ed] * IN_DIM + f]);
}

__global__ void k_scatter384(const int* __restrict__ src, const int* __restrict__ dst,
                             const float* __restrict__ h, float* __restrict__ agg, int e) {
    int idx = blockIdx.x * blockDim.x + threadIdx.x;
    if (idx >= e * 96) return;
    int ed = idx / 96;
    int c  = (idx % 96) * 4;
    int s = src[ed], d = dst[ed];
    float4 v = *(const float4*)(h + (size_t)s * HID + c);
    float* p = agg + (size_t)d * HID + c;
    atomicAdd(p + 0, v.x);
    atomicAdd(p + 1, v.y);
    atomicAdd(p + 2, v.z);
    atomicAdd(p + 3, v.w);
}

// ---------------------------------------------------------------------------
// Layer 0 SAGE: K=10, 16 rows/block, 384 threads (one per out col)
// ---------------------------------------------------------------------------
__global__ void k_layer0(const float* __restrict__ agg, const float* __restrict__ x,
                         const float* __restrict__ invc,
                         const float* __restrict__ Wl, const float* __restrict__ bl,
                         const float* __restrict__ Wr,
                         const float* __restrict__ bng, const float* __restrict__ bnb,
                         const float* __restrict__ bnm, const float* __restrict__ bnv,
                         float* __restrict__ out, int n) {
    __shared__ float sA[16][IN_DIM];
    __shared__ float sX[16][IN_DIM];
    __shared__ float sInv[16];
    __shared__ float red[16];
    int t = threadIdx.x;
    int row0 = blockIdx.x * 16;

    if (t < 160) {
        int r = t / IN_DIM, k = t % IN_DIM;
        int row = row0 + r;
        sA[r][k] = (row < n) ? agg[(size_t)row * IN_DIM + k] : 0.0f;
    } else if (t < 320) {
        int q = t - 160;
        int r = q / IN_DIM, k = q % IN_DIM;
        int row = row0 + r;
        sX[r][k] = (row < n) ? x[(size_t)row * IN_DIM + k] : 0.0f;
    } else if (t < 336) {
        int r = t - 320, row = row0 + r;
        sInv[r] = (row < n) ? invc[row] : 1.0f;
    } else if (t < 352) {
        red[t - 336] = 0.0f;
    }
    __syncthreads();

    int j = t;
    float wl[IN_DIM], wr[IN_DIM];
#pragma unroll
    for (int k = 0; k < IN_DIM; k++) {
        wl[k] = Wl[j * IN_DIM + k];
        wr[k] = Wr[j * IN_DIM + k];
    }
    float bb = bl[j];

    float v[16];
#pragma unroll
    for (int r = 0; r < 16; r++) {
        float iv = sInv[r];
        float s = bb;
#pragma unroll
        for (int k = 0; k < IN_DIM; k++)
            s += sA[r][k] * iv * wl[k] + sX[r][k] * wr[k];
        v[r] = s;
    }

    int lane = t & 31;
#pragma unroll
    for (int r = 0; r < 16; r++) {
        float p = v[r] * v[r];
#pragma unroll
        for (int o = 16; o > 0; o >>= 1) p += __shfl_xor_sync(0xFFFFFFFFu, p, o);
        if (lane == 0) atomicAdd(&red[r], p);
    }
    __syncthreads();

    float gm = bng[j], gb = bnb[j], mm = bnm[j], vv = bnv[j];
    float bscale = rsqrtf(vv + BN_EPS) * gm;
#pragma unroll
    for (int r = 0; r < 16; r++) {
        int row = row0 + r;
        if (row >= n) continue;
        float sc = 1.0f / fmaxf(sqrtf(red[r]), 1e-12f);
        float val = v[r] * sc;
        val = (val - mm) * bscale + gb;
        val = (val > 0.0f) ? val : expm1f(val);
        out[(size_t)row * HID + j] = val;
    }
}

// ---------------------------------------------------------------------------
// tf32 mma.sync fused GEMM
//   C[64, 384] = A1 * W1^T (+ A2 * W2^T) + bias ; invc row-scale on A1
//   epi 0: L2-normalize row, BN, ELU ; epi 1: BN, ReLU
// 512 threads = 16 warps; warp tile 32x48 (2 m16 x 6 n8), BK=16.
// SMEM stride 20 floats: conflict-free fragment loads, 16B-aligned stores.
// ---------------------------------------------------------------------------
#define ASTR 20

__global__ void __launch_bounds__(512, 1)
k_mma(const float* __restrict__ A1, const float* __restrict__ W1,
      const float* __restrict__ bias,
      const float* __restrict__ A2, const float* __restrict__ W2,
      const float* __restrict__ invc,
      const float* __restrict__ bng, const float* __restrict__ bnb,
      const float* __restrict__ bnm, const float* __restrict__ bnv,
      float* __restrict__ out, int nrows, int epi) {
    __shared__ float As[64 * ASTR];
    __shared__ float Ws[384 * ASTR];
    __shared__ float sSB[HID], sS2[HID], sAD[HID];
    __shared__ float red[64];
    __shared__ float sInv[64];

    const int tid  = threadIdx.x;
    const int lane = tid & 31;
    const int wid  = tid >> 5;
    const int rw   = wid & 1;          // row-warp 0..1
    const int cw   = wid >> 1;         // col-warp 0..7
    const int g    = lane >> 2;        // 0..7
    const int t4   = lane & 3;         // 0..3
    const int warpRow = rw * 32;
    const int cb   = cw * 48;
    const int rb   = blockIdx.x * 64;

    const bool useInv = (invc != nullptr);

    // BN constants
    for (int c = tid; c < HID; c += 512) {
        float s2 = rsqrtf(bnv[c] + BN_EPS) * bng[c];
        sSB[c] = bias[c];
        sS2[c] = s2;
        sAD[c] = bnb[c] - bnm[c] * s2;
    }
    if (tid < 64) {
        red[tid] = 0.0f;
        int row = rb + tid;
        sInv[tid] = (useInv && row < nrows) ? invc[row] : 1.0f;
    }
    __syncthreads();

    // loader indices
    const int ar = tid >> 2, aq = tid & 3;          // A: threads 0..255
    int wr[3], wq[3];
#pragma unroll
    for (int i = 0; i < 3; i++) {
        int idx = tid + i * 512;
        wr[i] = idx >> 2;
        wq[i] = idx & 3;
    }

    const int npass = (A2 == nullptr) ? 1 : 2;
    const int S = 24 * npass;

    float acc[2][6][4];
#pragma unroll
    for (int mt = 0; mt < 2; mt++)
#pragma unroll
        for (int nt = 0; nt < 6; nt++)
#pragma unroll
            for (int q = 0; q < 4; q++) acc[mt][nt][q] = 0.0f;

    float4 avP = make_float4(0.f, 0.f, 0.f, 0.f);
    float4 wvP[3];

    // prologue fetch it=0
    {
        const float* A = A1;
        const float* W = W1;
        if (tid < 256) {
            int row = rb + ar;
            if (row < nrows) {
                avP = *(const float4*)(A + (size_t)row * HID + aq * 4);
                float iv = sInv[ar];
                avP.x *= iv; avP.y *= iv; avP.z *= iv; avP.w *= iv;
            }
        }
#pragma unroll
        for (int i = 0; i < 3; i++)
            wvP[i] = *(const float4*)(W + (size_t)wr[i] * HID + wq[i] * 4);
    }

    for (int it = 0; it < S; it++) {
        // stage to SMEM (converted to tf32)
        if (tid < 256) {
            uint32_t* p = (uint32_t*)&As[ar * ASTR + aq * 4];
            p[0] = f2tf32(avP.x); p[1] = f2tf32(avP.y);
            p[2] = f2tf32(avP.z); p[3] = f2tf32(avP.w);
        }
#pragma unroll
        for (int i = 0; i < 3; i++) {
            uint32_t* p = (uint32_t*)&Ws[wr[i] * ASTR + wq[i] * 4];
            p[0] = f2tf32(wvP[i].x); p[1] = f2tf32(wvP[i].y);
            p[2] = f2tf32(wvP[i].z); p[3] = f2tf32(wvP[i].w);
        }
        __syncthreads();

        // prefetch next iter
        if (it + 1 < S) {
            const int itn = it + 1;
            const int pass = itn / 24;
            const int k0 = (itn % 24) * 16;
            const float* A = pass ? A2 : A1;
            const float* W = pass ? W2 : W1;
            if (tid < 256) {
                int row = rb + ar;
                avP = make_float4(0.f, 0.f, 0.f, 0.f);
                if (row < nrows) {
                    avP = *(const float4*)(A + (size_t)row * HID + k0 + aq * 4);
                    if (pass == 0 && useInv) {
                        float iv = sInv[ar];
                        avP.x *= iv; avP.y *= iv; avP.z *= iv; avP.w *= iv;
                    }
                }
            }
#pragma unroll
            for (int i = 0; i < 3; i++)
                wvP[i] = *(const float4*)(W + (size_t)wr[i] * HID + k0 + wq[i] * 4);
        }

        // compute: 2 k8 steps
#pragma unroll
        for (int ks = 0; ks < 2; ks++) {
            const int kk = ks * 8 + t4;
            uint32_t a[2][4];
#pragma unroll
            for (int mt = 0; mt < 2; mt++) {
                int r0 = warpRow + mt * 16 + g;
                a[mt][0] = __float_as_uint(As[r0 * ASTR + kk]);
                a[mt][1] = __float_as_uint(As[(r0 + 8) * ASTR + kk]);
                a[mt][2] = __float_as_uint(As[r0 * ASTR + kk + 4]);
                a[mt][3] = __float_as_uint(As[(r0 + 8) * ASTR + kk + 4]);
            }
#pragma unroll
            for (int nt = 0; nt < 6; nt++) {
                int n0 = cb + nt * 8 + g;
                uint32_t b0 = __float_as_uint(Ws[n0 * ASTR + kk]);
                uint32_t b1 = __float_as_uint(Ws[n0 * ASTR + kk + 4]);
                mma_tf32(acc[0][nt], a[0][0], a[0][1], a[0][2], a[0][3], b0, b1);
                mma_tf32(acc[1][nt], a[1][0], a[1][1], a[1][2], a[1][3], b0, b1);
            }
        }
        __syncthreads();
    }

    // ---- epilogue ----
    // bias add
#pragma unroll
    for (int nt = 0; nt < 6; nt++) {
        int col = cb + nt * 8 + 2 * t4;
        float b0 = sSB[col], b1 = sSB[col + 1];
#pragma unroll
        for (int mt = 0; mt < 2; mt++) {
            acc[mt][nt][0] += b0; acc[mt][nt][1] += b1;
            acc[mt][nt][2] += b0; acc[mt][nt][3] += b1;
        }
    }

    float sc0[2] = {1.0f, 1.0f}, sc1[2] = {1.0f, 1.0f};
    if (epi == 0) {
#pragma unroll
        for (int mt = 0; mt < 2; mt++) {
            float s0 = 0.0f, s1 = 0.0f;
#pragma unroll
            for (int nt = 0; nt < 6; nt++) {
                s0 = fmaf(acc[mt][nt][0], acc[mt][nt][0], s0);
                s0 = fmaf(acc[mt][nt][1], acc[mt][nt][1], s0);
                s1 = fmaf(acc[mt][nt][2], acc[mt][nt][2], s1);
                s1 = fmaf(acc[mt][nt][3], acc[mt][nt][3], s1);
            }
            s0 += __shfl_xor_sync(0xFFFFFFFFu, s0, 1);
            s0 += __shfl_xor_sync(0xFFFFFFFFu, s0, 2);
            s1 += __shfl_xor_sync(0xFFFFFFFFu, s1, 1);
            s1 += __shfl_xor_sync(0xFFFFFFFFu, s1, 2);
            if (t4 == 0) {
                atomicAdd(&red[warpRow + mt * 16 + g], s0);
                atomicAdd(&red[warpRow + mt * 16 + g + 8], s1);
            }
        }
        __syncthreads();
#pragma unroll
        for (int mt = 0; mt < 2; mt++) {
            sc0[mt] = 1.0f / fmaxf(sqrtf(red[warpRow + mt * 16 + g]), 1e-12f);
            sc1[mt] = 1.0f / fmaxf(sqrtf(red[warpRow + mt * 16 + g + 8]), 1e-12f);
        }
    }

#pragma unroll
    for (int mt = 0; mt < 2; mt++) {
        int row0 = rb + warpRow + mt * 16 + g;
        int row1 = row0 + 8;
        bool v0 = (row0 < nrows), v1 = (row1 < nrows);
#pragma unroll
        for (int nt = 0; nt < 6; nt++) {
            int col = cb + nt * 8 + 2 * t4;
            float m0 = sS2[col], m1 = sS2[col + 1];
            float d0 = sAD[col], d1 = sAD[col + 1];
            float x0 = acc[mt][nt][0] * sc0[mt] * m0 + d0;
            float x1 = acc[mt][nt][1] * sc0[mt] * m1 + d1;
            float x2 = acc[mt][nt][2] * sc1[mt] * m0 + d0;
            float x3 = acc[mt][nt][3] * sc1[mt] * m1 + d1;
            if (epi == 0) {
                x0 = (x0 > 0.0f) ? x0 : expm1f(x0);
                x1 = (x1 > 0.0f) ? x1 : expm1f(x1);
                x2 = (x2 > 0.0f) ? x2 : expm1f(x2);
                x3 = (x3 > 0.0f) ? x3 : expm1f(x3);
            } else {
                x0 = fmaxf(x0, 0.0f); x1 = fmaxf(x1, 0.0f);
                x2 = fmaxf(x2, 0.0f); x3 = fmaxf(x3, 0.0f);
            }
            if (v0) *(float2*)(out + (size_t)row0 * HID + col) = make_float2(x0, x1);
            if (v1) *(float2*)(out + (size_t)row1 * HID + col) = make_float2(x2, x3);
        }
    }
}

// ---------------------------------------------------------------------------
// Final projection: out[N,3] = h @ Wp2^T + bp2. One warp per row.
// ---------------------------------------------------------------------------
__global__ void k_final(const float* __restrict__ h, const float* __restrict__ W,
                        const float* __restrict__ b, float* __restrict__ out, int n) {
    int w = (blockIdx.x * blockDim.x + threadIdx.x) >> 5;
    int lane = threadIdx.x & 31;
    if (w >= n) return;
    const float* hr = h + (size_t)w * HID;
    float a0 = 0.0f, a1 = 0.0f, a2 = 0.0f;
#pragma unroll
    for (int k = lane; k < HID; k += 32) {
        float hv = hr[k];
        a0 = fmaf(hv, W[k], a0);
        a1 = fmaf(hv, W[HID + k], a1);
        a2 = fmaf(hv, W[2 * HID + k], a2);
    }
#pragma unroll
    for (int o = 16; o > 0; o >>= 1) {
        a0 += __shfl_xor_sync(0xFFFFFFFFu, a0, o);
        a1 += __shfl_xor_sync(0xFFFFFFFFu, a1, o);
        a2 += __shfl_xor_sync(0xFFFFFFFFu, a2, o);
    }
    if (lane == 0) {
        out[(size_t)w * 3 + 0] = a0 + b[0];
        out[(size_t)w * 3 + 1] = a1 + b[1];
        out[(size_t)w * 3 + 2] = a2 + b[2];
    }
}

// ---------------------------------------------------------------------------
extern "C" void kernel_launch(void* const* d_in, const int* in_sizes, int n_in,
                              void* d_out, int out_size) {
    const float* x    = (const float*)d_in[0];
    const int*   ei   = (const int*)  d_in[1];
    const float* Wl0  = (const float*)d_in[2];
    const float* bl0  = (const float*)d_in[3];
    const float* Wr0  = (const float*)d_in[4];
    const float* Wl   = (const float*)d_in[5];
    const float* bl   = (const float*)d_in[6];
    const float* Wr   = (const float*)d_in[7];
    const float* bng  = (const float*)d_in[8];
    const float* bnb  = (const float*)d_in[9];
    const float* bnm  = (const float*)d_in[10];
    const float* bnv  = (const float*)d_in[11];
    const float* Wp0  = (const float*)d_in[12];
    const float* bp0  = (const float*)d_in[13];
    const float* Wp1  = (const float*)d_in[14];
    const float* bp1  = (const float*)d_in[15];
    const float* Wp2  = (const float*)d_in[16];
    const float* bp2  = (const float*)d_in[17];
    const float* pg   = (const float*)d_in[18];
    const float* pb   = (const float*)d_in[19];
    const float* pm   = (const float*)d_in[20];
    const float* pv   = (const float*)d_in[21];

    const int* src = ei;
    const int* dst = ei + EE;

    float *hA, *hB, *agg, *cnt, *inv;
    cudaGetSymbolAddress((void**)&hA,  g_bufA);
    cudaGetSymbolAddress((void**)&hB,  g_bufB);
    cudaGetSymbolAddress((void**)&agg, g_agg);
    cudaGetSymbolAddress((void**)&cnt, g_cnt);
    cudaGetSymbolAddress((void**)&inv, g_inv);

    // degree + inverse
    cudaMemsetAsync(cnt, 0, (size_t)NN * sizeof(float));
    k_count<<<(EE + 255) / 256, 256>>>(dst, cnt, EE);
    k_inv<<<(NN + 255) / 256, 256>>>(cnt, inv, NN);

    // layer 0 (K=10)
    cudaMemsetAsync(agg, 0, (size_t)NN * IN_DIM * sizeof(float));
    k_scatter10<<<(EE * IN_DIM + 255) / 256, 256>>>(src, dst, x, agg, EE);
    k_layer0<<<(NN + 15) / 16, 384>>>(agg, x, inv, Wl0, bl0, Wr0,
                                      bng, bnb, bnm, bnv, hA, NN);

    // layers 1..4: scatter + dual tf32 mma GEMM
    const int gblocks = (NN + 63) / 64;
    for (int t = 1; t < TT; t++) {
        cudaMemsetAsync(agg, 0, (size_t)NN * HID * sizeof(float));
        k_scatter384<<<(EE * 96 + 255) / 256, 256>>>(src, dst, hA, agg, EE);
        k_mma<<<gblocks, 512>>>(
            agg, Wl + (size_t)(t - 1) * HID * HID, bl + (t - 1) * HID,
            hA,  Wr + (size_t)(t - 1) * HID * HID,
            inv,
            bng + t * HID, bnb + t * HID, bnm + t * HID, bnv + t * HID,
            hB, NN, 0);
        float* tmp = hA; hA = hB; hB = tmp;
    }

    // projection MLP
    k_mma<<<gblocks, 512>>>(hA, Wp0, bp0, nullptr, nullptr, nullptr,
                            pg, pb, pm, pv, hB, NN, 1);
    k_mma<<<gblocks, 512>>>(hB, Wp1, bp1, nullptr, nullptr, nullptr,
                            pg + HID, pb + HID, pm + HID, pv + HID, hA, NN, 1);
    k_final<<<(NN + 7) / 8, 256>>>(hA, Wp2, bp2, (float*)d_out, NN);

    (void)in_sizes; (void)n_in; (void)out_size;
}

// round 5
// speedup vs baseline: 4.1504x; 1.2739x over previous
#include <cuda_runtime.h>
#include <math.h>
#include <cstdint>

#define NN 100000
#define EE 300000
#define IN_DIM 10
#define HID 384
#define TT 5
#define BN_EPS 1e-5f

#define SCAN_B 1024
#define NSCANB ((NN + SCAN_B - 1) / SCAN_B)   // 98

// Static scratch (allocation-free rule)
__device__ float g_bufA[(size_t)NN * HID];
__device__ float g_bufB[(size_t)NN * HID];
__device__ float g_agg [(size_t)NN * HID];
__device__ int   g_deg [NN];
__device__ int   g_inc [NN];
__device__ int   g_rowptr[NN + 1];
__device__ int   g_cur [NN];
__device__ int   g_csrc[EE];
__device__ int   g_bsum[128];

// ---------------------------------------------------------------------------
// helpers
// ---------------------------------------------------------------------------
__device__ __forceinline__ uint32_t f2tf32(float f) {
    uint32_t u;
    asm("cvt.rna.tf32.f32 %0, %1;" : "=r"(u) : "f"(f));
    return u;
}

__device__ __forceinline__ void mma_tf32(float* c,
                                         uint32_t a0, uint32_t a1, uint32_t a2, uint32_t a3,
                                         uint32_t b0, uint32_t b1) {
    asm volatile("mma.sync.aligned.m16n8k8.row.col.f32.tf32.tf32.f32 "
                 "{%0,%1,%2,%3}, {%4,%5,%6,%7}, {%8,%9}, {%0,%1,%2,%3};"
                 : "+f"(c[0]), "+f"(c[1]), "+f"(c[2]), "+f"(c[3])
                 : "r"(a0), "r"(a1), "r"(a2), "r"(a3), "r"(b0), "r"(b1));
}

// ---------------------------------------------------------------------------
// CSR build
// ---------------------------------------------------------------------------
__global__ void k_hist(const int* __restrict__ dst, int* __restrict__ deg, int e) {
    int i = blockIdx.x * blockDim.x + threadIdx.x;
    if (i < e) atomicAdd(&deg[dst[i]], 1);
}

__global__ void k_scan_block(const int* __restrict__ deg, int* __restrict__ inc,
                             int* __restrict__ bsum, int n) {
    __shared__ int s[SCAN_B];
    int i = blockIdx.x * SCAN_B + threadIdx.x;
    s[threadIdx.x] = (i < n) ? deg[i] : 0;
    __syncthreads();
#pragma unroll
    for (int o = 1; o < SCAN_B; o <<= 1) {
        int t = (threadIdx.x >= o) ? s[threadIdx.x - o] : 0;
        __syncthreads();
        s[threadIdx.x] += t;
        __syncthreads();
    }
    if (i < n) inc[i] = s[threadIdx.x];
    if (threadIdx.x == SCAN_B - 1) bsum[blockIdx.x] = s[SCAN_B - 1];
}

__global__ void k_scan_bsum(int* __restrict__ bsum, int nb) {
    __shared__ int s[128];
    if (threadIdx.x < nb) s[threadIdx.x] = bsum[threadIdx.x];
    __syncthreads();
    if (threadIdx.x == 0) {
        int run = 0;
        for (int i = 0; i < nb; i++) { run += s[i]; s[i] = run; }
    }
    __syncthreads();
    if (threadIdx.x < nb) bsum[threadIdx.x] = s[threadIdx.x];
}

__global__ void k_csr_fin(const int* __restrict__ deg, const int* __restrict__ inc,
                          const int* __restrict__ bsum,
                          int* __restrict__ rowptr, int* __restrict__ cur, int n) {
    int i = blockIdx.x * blockDim.x + threadIdx.x;
    if (i >= n) return;
    int b = i / SCAN_B;
    int total = inc[i] + (b > 0 ? bsum[b - 1] : 0);
    rowptr[i + 1] = total;
    cur[i] = total - deg[i];
    if (i == 0) rowptr[0] = 0;
}

__global__ void k_fill(const int* __restrict__ src, const int* __restrict__ dst,
                       int* __restrict__ cur, int* __restrict__ csrc, int e) {
    int i = blockIdx.x * blockDim.x + threadIdx.x;
    if (i >= e) return;
    int pos = atomicAdd(&cur[dst[i]], 1);
    csrc[pos] = src[i];
}

// ---------------------------------------------------------------------------
// CSR mean-gather, width 384: one warp per node, coalesced rows
// ---------------------------------------------------------------------------
__global__ void k_gather384(const int* __restrict__ rowptr, const int* __restrict__ csrc,
                            const float* __restrict__ h, float* __restrict__ agg, int n) {
    int node = (blockIdx.x * blockDim.x + threadIdx.x) >> 5;
    int lane = threadIdx.x & 31;
    if (node >= n) return;
    int beg = rowptr[node], end = rowptr[node + 1];
    float4 a0 = make_float4(0.f, 0.f, 0.f, 0.f);
    float4 a1 = a0, a2 = a0;
    for (int e = beg; e < end; e++) {
        const float4* p = (const float4*)(h + (size_t)csrc[e] * HID) + lane;
        float4 v0 = p[0], v1 = p[32], v2 = p[64];
        a0.x += v0.x; a0.y += v0.y; a0.z += v0.z; a0.w += v0.w;
        a1.x += v1.x; a1.y += v1.y; a1.z += v1.z; a1.w += v1.w;
        a2.x += v2.x; a2.y += v2.y; a2.z += v2.z; a2.w += v2.w;
    }
    float iv = 1.0f / fmaxf((float)(end - beg), 1.0f);
    a0.x *= iv; a0.y *= iv; a0.z *= iv; a0.w *= iv;
    a1.x *= iv; a1.y *= iv; a1.z *= iv; a1.w *= iv;
    a2.x *= iv; a2.y *= iv; a2.z *= iv; a2.w *= iv;
    float4* o = (float4*)(agg + (size_t)node * HID) + lane;
    o[0] = a0; o[32] = a1; o[64] = a2;
}

// width 10: thread per (node, feature)
__global__ void k_gather10(const int* __restrict__ rowptr, const int* __restrict__ csrc,
                           const float* __restrict__ x, float* __restrict__ agg, int n) {
    int idx = blockIdx.x * blockDim.x + threadIdx.x;
    if (idx >= n * IN_DIM) return;
    int node = idx / IN_DIM, f = idx % IN_DIM;
    int beg = rowptr[node], end = rowptr[node + 1];
    float a = 0.0f;
    for (int e = beg; e < end; e++)
        a += x[(size_t)csrc[e] * IN_DIM + f];
    agg[idx] = a / fmaxf((float)(end - beg), 1.0f);
}

// ---------------------------------------------------------------------------
// Layer 0 SAGE: K=10, 16 rows/block, 384 threads (agg is already the mean)
// ---------------------------------------------------------------------------
__global__ void k_layer0(const float* __restrict__ agg, const float* __restrict__ x,
                         const float* __restrict__ Wl, const float* __restrict__ bl,
                         const float* __restrict__ Wr,
                         const float* __restrict__ bng, const float* __restrict__ bnb,
                         const float* __restrict__ bnm, const float* __restrict__ bnv,
                         float* __restrict__ out, int n) {
    __shared__ float sA[16][IN_DIM];
    __shared__ float sX[16][IN_DIM];
    __shared__ float red[16];
    int t = threadIdx.x;
    int row0 = blockIdx.x * 16;

    if (t < 160) {
        int r = t / IN_DIM, k = t % IN_DIM;
        int row = row0 + r;
        sA[r][k] = (row < n) ? agg[(size_t)row * IN_DIM + k] : 0.0f;
    } else if (t < 320) {
        int q = t - 160;
        int r = q / IN_DIM, k = q % IN_DIM;
        int row = row0 + r;
        sX[r][k] = (row < n) ? x[(size_t)row * IN_DIM + k] : 0.0f;
    } else if (t < 336) {
        red[t - 320] = 0.0f;
    }
    __syncthreads();

    int j = t;
    float wl[IN_DIM], wr[IN_DIM];
#pragma unroll
    for (int k = 0; k < IN_DIM; k++) {
        wl[k] = Wl[j * IN_DIM + k];
        wr[k] = Wr[j * IN_DIM + k];
    }
    float bb = bl[j];

    float v[16];
#pragma unroll
    for (int r = 0; r < 16; r++) {
        float s = bb;
#pragma unroll
        for (int k = 0; k < IN_DIM; k++)
            s += sA[r][k] * wl[k] + sX[r][k] * wr[k];
        v[r] = s;
    }

    int lane = t & 31;
#pragma unroll
    for (int r = 0; r < 16; r++) {
        float p = v[r] * v[r];
#pragma unroll
        for (int o = 16; o > 0; o >>= 1) p += __shfl_xor_sync(0xFFFFFFFFu, p, o);
        if (lane == 0) atomicAdd(&red[r], p);
    }
    __syncthreads();

    float gm = bng[j], gb = bnb[j], mm = bnm[j], vv = bnv[j];
    float bscale = rsqrtf(vv + BN_EPS) * gm;
#pragma unroll
    for (int r = 0; r < 16; r++) {
        int row = row0 + r;
        if (row >= n) continue;
        float sc = 1.0f / fmaxf(sqrtf(red[r]), 1e-12f);
        float val = v[r] * sc;
        val = (val - mm) * bscale + gb;
        val = (val > 0.0f) ? val : expm1f(val);
        out[(size_t)row * HID + j] = val;
    }
}

// ---------------------------------------------------------------------------
// tf32 mma.sync fused GEMM (as round 4; invc path removed)
// C[64, 384] = A1 * W1^T (+ A2 * W2^T) + bias
// epi 0: L2-normalize row, BN, ELU ; epi 1: BN, ReLU
// ---------------------------------------------------------------------------
#define ASTR 20

__global__ void __launch_bounds__(512, 1)
k_mma(const float* __restrict__ A1, const float* __restrict__ W1,
      const float* __restrict__ bias,
      const float* __restrict__ A2, const float* __restrict__ W2,
      const float* __restrict__ bng, const float* __restrict__ bnb,
      const float* __restrict__ bnm, const float* __restrict__ bnv,
      float* __restrict__ out, int nrows, int epi) {
    __shared__ float As[64 * ASTR];
    __shared__ float Ws[384 * ASTR];
    __shared__ float sSB[HID], sS2[HID], sAD[HID];
    __shared__ float red[64];

    const int tid  = threadIdx.x;
    const int lane = tid & 31;
    const int wid  = tid >> 5;
    const int rw   = wid & 1;
    const int cw   = wid >> 1;
    const int g    = lane >> 2;
    const int t4   = lane & 3;
    const int warpRow = rw * 32;
    const int cb   = cw * 48;
    const int rb   = blockIdx.x * 64;

    for (int c = tid; c < HID; c += 512) {
        float s2 = rsqrtf(bnv[c] + BN_EPS) * bng[c];
        sSB[c] = bias[c];
        sS2[c] = s2;
        sAD[c] = bnb[c] - bnm[c] * s2;
    }
    if (tid < 64) red[tid] = 0.0f;
    __syncthreads();

    const int ar = tid >> 2, aq = tid & 3;
    int wr[3], wq[3];
#pragma unroll
    for (int i = 0; i < 3; i++) {
        int idx = tid + i * 512;
        wr[i] = idx >> 2;
        wq[i] = idx & 3;
    }

    const int npass = (A2 == nullptr) ? 1 : 2;
    const int S = 24 * npass;

    float acc[2][6][4];
#pragma unroll
    for (int mt = 0; mt < 2; mt++)
#pragma unroll
        for (int nt = 0; nt < 6; nt++)
#pragma unroll
            for (int q = 0; q < 4; q++) acc[mt][nt][q] = 0.0f;

    float4 avP = make_float4(0.f, 0.f, 0.f, 0.f);
    float4 wvP[3];

    {
        if (tid < 256) {
            int row = rb + ar;
            if (row < nrows)
                avP = *(const float4*)(A1 + (size_t)row * HID + aq * 4);
        }
#pragma unroll
        for (int i = 0; i < 3; i++)
            wvP[i] = *(const float4*)(W1 + (size_t)wr[i] * HID + wq[i] * 4);
    }

    for (int it = 0; it < S; it++) {
        if (tid < 256) {
            uint32_t* p = (uint32_t*)&As[ar * ASTR + aq * 4];
            p[0] = f2tf32(avP.x); p[1] = f2tf32(avP.y);
            p[2] = f2tf32(avP.z); p[3] = f2tf32(avP.w);
        }
#pragma unroll
        for (int i = 0; i < 3; i++) {
            uint32_t* p = (uint32_t*)&Ws[wr[i] * ASTR + wq[i] * 4];
            p[0] = f2tf32(wvP[i].x); p[1] = f2tf32(wvP[i].y);
            p[2] = f2tf32(wvP[i].z); p[3] = f2tf32(wvP[i].w);
        }
        __syncthreads();

        if (it + 1 < S) {
            const int itn = it + 1;
            const int pass = itn / 24;
            const int k0 = (itn % 24) * 16;
            const float* A = pass ? A2 : A1;
            const float* W = pass ? W2 : W1;
            if (tid < 256) {
                int row = rb + ar;
                avP = make_float4(0.f, 0.f, 0.f, 0.f);
                if (row < nrows)
                    avP = *(const float4*)(A + (size_t)row * HID + k0 + aq * 4);
            }
#pragma unroll
            for (int i = 0; i < 3; i++)
                wvP[i] = *(const float4*)(W + (size_t)wr[i] * HID + k0 + wq[i] * 4);
        }

#pragma unroll
        for (int ks = 0; ks < 2; ks++) {
            const int kk = ks * 8 + t4;
            uint32_t a[2][4];
#pragma unroll
            for (int mt = 0; mt < 2; mt++) {
                int r0 = warpRow + mt * 16 + g;
                a[mt][0] = __float_as_uint(As[r0 * ASTR + kk]);
                a[mt][1] = __float_as_uint(As[(r0 + 8) * ASTR + kk]);
                a[mt][2] = __float_as_uint(As[r0 * ASTR + kk + 4]);
                a[mt][3] = __float_as_uint(As[(r0 + 8) * ASTR + kk + 4]);
            }
#pragma unroll
            for (int nt = 0; nt < 6; nt++) {
                int n0 = cb + nt * 8 + g;
                uint32_t b0 = __float_as_uint(Ws[n0 * ASTR + kk]);
                uint32_t b1 = __float_as_uint(Ws[n0 * ASTR + kk + 4]);
                mma_tf32(acc[0][nt], a[0][0], a[0][1], a[0][2], a[0][3], b0, b1);
                mma_tf32(acc[1][nt], a[1][0], a[1][1], a[1][2], a[1][3], b0, b1);
            }
        }
        __syncthreads();
    }

    // ---- epilogue ----
#pragma unroll
    for (int nt = 0; nt < 6; nt++) {
        int col = cb + nt * 8 + 2 * t4;
        float b0 = sSB[col], b1 = sSB[col + 1];
#pragma unroll
        for (int mt = 0; mt < 2; mt++) {
            acc[mt][nt][0] += b0; acc[mt][nt][1] += b1;
            acc[mt][nt][2] += b0; acc[mt][nt][3] += b1;
        }
    }

    float sc0[2] = {1.0f, 1.0f}, sc1[2] = {1.0f, 1.0f};
    if (epi == 0) {
#pragma unroll
        for (int mt = 0; mt < 2; mt++) {
            float s0 = 0.0f, s1 = 0.0f;
#pragma unroll
            for (int nt = 0; nt < 6; nt++) {
                s0 = fmaf(acc[mt][nt][0], acc[mt][nt][0], s0);
                s0 = fmaf(acc[mt][nt][1], acc[mt][nt][1], s0);
                s1 = fmaf(acc[mt][nt][2], acc[mt][nt][2], s1);
                s1 = fmaf(acc[mt][nt][3], acc[mt][nt][3], s1);
            }
            s0 += __shfl_xor_sync(0xFFFFFFFFu, s0, 1);
            s0 += __shfl_xor_sync(0xFFFFFFFFu, s0, 2);
            s1 += __shfl_xor_sync(0xFFFFFFFFu, s1, 1);
            s1 += __shfl_xor_sync(0xFFFFFFFFu, s1, 2);
            if (t4 == 0) {
                atomicAdd(&red[warpRow + mt * 16 + g], s0);
                atomicAdd(&red[warpRow + mt * 16 + g + 8], s1);
            }
        }
        __syncthreads();
#pragma unroll
        for (int mt = 0; mt < 2; mt++) {
            sc0[mt] = 1.0f / fmaxf(sqrtf(red[warpRow + mt * 16 + g]), 1e-12f);
            sc1[mt] = 1.0f / fmaxf(sqrtf(red[warpRow + mt * 16 + g + 8]), 1e-12f);
        }
    }

#pragma unroll
    for (int mt = 0; mt < 2; mt++) {
        int row0 = rb + warpRow + mt * 16 + g;
        int row1 = row0 + 8;
        bool v0 = (row0 < nrows), v1 = (row1 < nrows);
#pragma unroll
        for (int nt = 0; nt < 6; nt++) {
            int col = cb + nt * 8 + 2 * t4;
            float m0 = sS2[col], m1 = sS2[col + 1];
            float d0 = sAD[col], d1 = sAD[col + 1];
            float x0 = acc[mt][nt][0] * sc0[mt] * m0 + d0;
            float x1 = acc[mt][nt][1] * sc0[mt] * m1 + d1;
            float x2 = acc[mt][nt][2] * sc1[mt] * m0 + d0;
            float x3 = acc[mt][nt][3] * sc1[mt] * m1 + d1;
            if (epi == 0) {
                x0 = (x0 > 0.0f) ? x0 : expm1f(x0);
                x1 = (x1 > 0.0f) ? x1 : expm1f(x1);
                x2 = (x2 > 0.0f) ? x2 : expm1f(x2);
                x3 = (x3 > 0.0f) ? x3 : expm1f(x3);
            } else {
                x0 = fmaxf(x0, 0.0f); x1 = fmaxf(x1, 0.0f);
                x2 = fmaxf(x2, 0.0f); x3 = fmaxf(x3, 0.0f);
            }
            if (v0) *(float2*)(out + (size_t)row0 * HID + col) = make_float2(x0, x1);
            if (v1) *(float2*)(out + (size_t)row1 * HID + col) = make_float2(x2, x3);
        }
    }
}

// ---------------------------------------------------------------------------
// Final projection: out[N,3] = h @ Wp2^T + bp2. One warp per row.
// ---------------------------------------------------------------------------
__global__ void k_final(const float* __restrict__ h, const float* __restrict__ W,
                        const float* __restrict__ b, float* __restrict__ out, int n) {
    int w = (blockIdx.x * blockDim.x + threadIdx.x) >> 5;
    int lane = threadIdx.x & 31;
    if (w >= n) return;
    const float* hr = h + (size_t)w * HID;
    float a0 = 0.0f, a1 = 0.0f, a2 = 0.0f;
#pragma unroll
    for (int k = lane; k < HID; k += 32) {
        float hv = hr[k];
        a0 = fmaf(hv, W[k], a0);
        a1 = fmaf(hv, W[HID + k], a1);
        a2 = fmaf(hv, W[2 * HID + k], a2);
    }
#pragma unroll
    for (int o = 16; o > 0; o >>= 1) {
        a0 += __shfl_xor_sync(0xFFFFFFFFu, a0, o);
        a1 += __shfl_xor_sync(0xFFFFFFFFu, a1, o);
        a2 += __shfl_xor_sync(0xFFFFFFFFu, a2, o);
    }
    if (lane == 0) {
        out[(size_t)w * 3 + 0] = a0 + b[0];
        out[(size_t)w * 3 + 1] = a1 + b[1];
        out[(size_t)w * 3 + 2] = a2 + b[2];
    }
}

// ---------------------------------------------------------------------------
extern "C" void kernel_launch(void* const* d_in, const int* in_sizes, int n_in,
                              void* d_out, int out_size) {
    const float* x    = (const float*)d_in[0];
    const int*   ei   = (const int*)  d_in[1];
    const float* Wl0  = (const float*)d_in[2];
    const float* bl0  = (const float*)d_in[3];
    const float* Wr0  = (const float*)d_in[4];
    const float* Wl   = (const float*)d_in[5];
    const float* bl   = (const float*)d_in[6];
    const float* Wr   = (const float*)d_in[7];
    const float* bng  = (const float*)d_in[8];
    const float* bnb  = (const float*)d_in[9];
    const float* bnm  = (const float*)d_in[10];
    const float* bnv  = (const float*)d_in[11];
    const float* Wp0  = (const float*)d_in[12];
    const float* bp0  = (const float*)d_in[13];
    const float* Wp1  = (const float*)d_in[14];
    const float* bp1  = (const float*)d_in[15];
    const float* Wp2  = (const float*)d_in[16];
    const float* bp2  = (const float*)d_in[17];
    const float* pg   = (const float*)d_in[18];
    const float* pb   = (const float*)d_in[19];
    const float* pm   = (const float*)d_in[20];
    const float* pv   = (const float*)d_in[21];

    const int* src = ei;
    const int* dst = ei + EE;

    float *hA, *hB, *agg;
    int *deg, *inc, *rowptr, *cur, *csrc, *bsum;
    cudaGetSymbolAddress((void**)&hA,     g_bufA);
    cudaGetSymbolAddress((void**)&hB,     g_bufB);
    cudaGetSymbolAddress((void**)&agg,    g_agg);
    cudaGetSymbolAddress((void**)&deg,    g_deg);
    cudaGetSymbolAddress((void**)&inc,    g_inc);
    cudaGetSymbolAddress((void**)&rowptr, g_rowptr);
    cudaGetSymbolAddress((void**)&cur,    g_cur);
    cudaGetSymbolAddress((void**)&csrc,   g_csrc);
    cudaGetSymbolAddress((void**)&bsum,   g_bsum);

    // ---- CSR build (once per call) ----
    cudaMemsetAsync(deg, 0, NN * sizeof(int));
    k_hist<<<(EE + 255) / 256, 256>>>(dst, deg, EE);
    k_scan_block<<<NSCANB, SCAN_B>>>(deg, inc, bsum, NN);
    k_scan_bsum<<<1, 128>>>(bsum, NSCANB);
    k_csr_fin<<<(NN + 255) / 256, 256>>>(deg, inc, bsum, rowptr, cur, NN);
    k_fill<<<(EE + 255) / 256, 256>>>(src, dst, cur, csrc, EE);

    // ---- layer 0 (K=10) ----
    k_gather10<<<(NN * IN_DIM + 255) / 256, 256>>>(rowptr, csrc, x, agg, NN);
    k_layer0<<<(NN + 15) / 16, 384>>>(agg, x, Wl0, bl0, Wr0,
                                      bng, bnb, bnm, bnv, hA, NN);

    // ---- layers 1..4: CSR gather + dual tf32 mma GEMM ----
    const int gblocks = (NN + 63) / 64;
    for (int t = 1; t < TT; t++) {
        k_gather384<<<(NN * 32 + 255) / 256, 256>>>(rowptr, csrc, hA, agg, NN);
        k_mma<<<gblocks, 512>>>(
            agg, Wl + (size_t)(t - 1) * HID * HID, bl + (t - 1) * HID,
            hA,  Wr + (size_t)(t - 1) * HID * HID,
            bng + t * HID, bnb + t * HID, bnm + t * HID, bnv + t * HID,
            hB, NN, 0);
        float* tmp = hA; hA = hB; hB = tmp;
    }

    // ---- projection MLP ----
    k_mma<<<gblocks, 512>>>(hA, Wp0, bp0, nullptr, nullptr,
                            pg, pb, pm, pv, hB, NN, 1);
    k_mma<<<gblocks, 512>>>(hB, Wp1, bp1, nullptr, nullptr,
                            pg + HID, pb + HID, pm + HID, pv + HID, hA, NN, 1);
    k_final<<<(NN + 7) / 8, 256>>>(hA, Wp2, bp2, (float*)d_out, NN);

    (void)in_sizes; (void)n_in; (void)out_size;
}